// round 6
// baseline (speedup 1.0000x reference)
#include <cuda_runtime.h>
#include <cuda_bf16.h>
#include <math.h>

#define NN  50000
#define EE  800000
#define INC 512
#define HH  64
#define OC  40
#define NL  64
#define NBLK ((NN + 1023) / 1024)   // 49 scan blocks
#define NBUN ((NN + 3) / 4)         // 12500 bundles (exact: 12500*4 == NN)

// ---------------- device scratch ----------------
__device__ float g_dinv[NN];
__device__ int   g_cnt[NN];
__device__ int   g_rowptr[NN + 1];
__device__ int   g_bsum[NBLK];
__device__ int   g_flag[64];
__device__ int   g_work[NL];
__device__ int   g_fill[NN];
__device__ int   g_col[EE];
__device__ float g_val[EE];
__device__ float g_x0[NN * HH];
__device__ float g_hbuf[2][NN * HH];
__device__ int   g_is64;

// ---------------- launch 0: lin1 (+ zero counts + int64 detect) ----------------
__global__ __launch_bounds__(256) void k_lin1(const float* __restrict__ x,
                                              const float* __restrict__ w1,
                                              const float* __restrict__ b1,
                                              const int* __restrict__ ei32) {
    int gtid = blockIdx.x * 256 + threadIdx.x;
    if (gtid < NN) g_cnt[gtid] = 0;
    if (gtid == 0) {
        int all0 = 1;
        for (int j = 0; j < 64; j++)
            if (ei32[2 * j + 1] != 0) all0 = 0;
        g_is64 = all0;
    }

    __shared__ float xsT[32][129];
    __shared__ float ws[32 * 64];
    int t = threadIdx.x;
    int half = t >> 7;
    int nl = t & 127;
    int node0 = blockIdx.x * 128;

    float acc[32];
#pragma unroll
    for (int c = 0; c < 32; c++) acc[c] = 0.f;

    for (int kt = 0; kt < INC; kt += 32) {
        for (int i = t; i < 32 * 64; i += 256)
            ws[i] = w1[(kt + (i >> 6)) * 64 + (i & 63)];
        for (int i = t; i < 1024; i += 256) {
            int r = i >> 3, c4 = i & 7;
            int node = node0 + r;
            float4 v = make_float4(0.f, 0.f, 0.f, 0.f);
            if (node < NN)
                v = *(const float4*)&x[(size_t)node * INC + kt + c4 * 4];
            xsT[c4 * 4 + 0][r] = v.x;
            xsT[c4 * 4 + 1][r] = v.y;
            xsT[c4 * 4 + 2][r] = v.z;
            xsT[c4 * 4 + 3][r] = v.w;
        }
        __syncthreads();
#pragma unroll 4
        for (int k = 0; k < 32; k++) {
            float xv = xsT[k][nl];
            const float4* wr = (const float4*)&ws[k * 64 + half * 32];
#pragma unroll
            for (int c4 = 0; c4 < 8; c4++) {
                float4 w4 = wr[c4];
                acc[c4 * 4 + 0] += xv * w4.x;
                acc[c4 * 4 + 1] += xv * w4.y;
                acc[c4 * 4 + 2] += xv * w4.z;
                acc[c4 * 4 + 3] += xv * w4.w;
            }
        }
        __syncthreads();
    }
    int node = node0 + nl;
    if (node < NN) {
        float* px = &g_x0[node * 64 + half * 32];
        float* ph = &g_hbuf[0][node * 64 + half * 32];
#pragma unroll
        for (int c4 = 0; c4 < 8; c4++) {
            float4 v;
            v.x = fmaxf(acc[c4 * 4 + 0] + b1[half * 32 + c4 * 4 + 0], 0.f);
            v.y = fmaxf(acc[c4 * 4 + 1] + b1[half * 32 + c4 * 4 + 1], 0.f);
            v.z = fmaxf(acc[c4 * 4 + 2] + b1[half * 32 + c4 * 4 + 2], 0.f);
            v.w = fmaxf(acc[c4 * 4 + 3] + b1[half * 32 + c4 * 4 + 3], 0.f);
            *(float4*)&px[c4 * 4] = v;
            *(float4*)&ph[c4 * 4] = v;
        }
    }
}

// ---------------- launch 1: count (+ reset lookback flags) ----------------
__global__ void k_count(const void* eiv) {
    int e = blockIdx.x * blockDim.x + threadIdx.x;
    if (e < 64) g_flag[e] = 0;
    if (e >= EE) return;
    int d;
    if (g_is64) d = (int)((const long long*)eiv)[EE + e];
    else        d = ((const int*)eiv)[EE + e];
    atomicAdd(&g_cnt[d], 1);
}

// ---------------- launch 2: single-pass scan (decoupled aggregates) ----------------
__global__ __launch_bounds__(1024) void k_scan() {
    __shared__ int wsum[32];
    __shared__ int pred[64];
    int t = threadIdx.x, b = blockIdx.x;
    int i = b * 1024 + t;
    int v = (i < NN) ? g_cnt[i] : 0;
    int lane = t & 31, wid = t >> 5;
    int s = v;
#pragma unroll
    for (int o = 1; o < 32; o <<= 1) {
        int u = __shfl_up_sync(0xffffffffu, s, o);
        if (lane >= o) s += u;
    }
    if (lane == 31) wsum[wid] = s;
    __syncthreads();
    if (wid == 0) {
        int ws = wsum[lane];
#pragma unroll
        for (int o = 1; o < 32; o <<= 1) {
            int u = __shfl_up_sync(0xffffffffu, ws, o);
            if (lane >= o) ws += u;
        }
        wsum[lane] = ws;
    }
    __syncthreads();
    int excl = s - v + (wid > 0 ? wsum[wid - 1] : 0);
    if (t == 1023) {
        g_bsum[b] = excl + v;        // block aggregate
        __threadfence();
        atomicExch(&g_flag[b], 1);
    }
    // gather predecessor aggregates
    if (t < 64) {
        int pv = 0;
        if (t < b) {
            while (atomicAdd(&g_flag[t], 0) == 0) {}
            pv = g_bsum[t];
        }
        pred[t] = pv;
    }
    __syncthreads();
    // reduce 64 -> 1
    for (int o = 32; o > 0; o >>= 1) {
        if (t < o) pred[t] += pred[t + o];
        __syncthreads();
    }
    int off = pred[0];
    if (i < NN) {
        g_rowptr[i] = excl + off;
        g_dinv[i] = rsqrtf((float)(v + 1));
        g_fill[i] = 0;
    }
    if (b == 0 && t < NL) g_work[t] = 0;
    if (i == 0) g_rowptr[NN] = EE;
}

// ---------------- launch 3: fill CSR ----------------
__global__ void k_fill(const void* eiv) {
    int e = blockIdx.x * blockDim.x + threadIdx.x;
    if (e >= EE) return;
    int s, d;
    if (g_is64) {
        const long long* ei = (const long long*)eiv;
        s = (int)ei[e];
        d = (int)ei[EE + e];
    } else {
        const int* ei = (const int*)eiv;
        s = ei[e];
        d = ei[EE + e];
    }
    int pos = g_rowptr[d] + atomicAdd(&g_fill[d], 1);
    g_col[pos] = s;
    g_val[pos] = g_dinv[s] * g_dinv[d];
}

// ---------------- launches 4..67: fused GCNII layer ----------------
// warp = one 4-node bundle from an atomic work queue; z staged directly in
// smem (transposed), no z registers; shared-W GEMM amortized over 4 nodes.
__global__ __launch_bounds__(256) void k_layer(const float* __restrict__ W,
                                               float beta, int l, int p) {
    __shared__ float ws[64 * 64];
    __shared__ float zqf[8][256];   // [warp][k*4 + q]
    int t = threadIdx.x, w = t >> 5, lane = t & 31;
    int l2 = lane * 2;
    int hl = lane >> 4;          // edge parity within pair
    int fl = lane & 15;          // feature quad id
    for (int i = t; i < 4096; i += 256) ws[i] = W[i];
    __syncthreads();

    const float4* __restrict__ hin4 = (const float4*)g_hbuf[p];
    const float4* __restrict__ x04 = (const float4*)g_x0;
    float* __restrict__ hout = g_hbuf[p ^ 1];
    float ob = 1.f - beta;

    for (;;) {
        int b;
        if (lane == 0) b = atomicAdd(&g_work[l], 1);
        b = __shfl_sync(0xffffffffu, b, 0);
        if (b >= NBUN) break;
        int base = b * 4;   // base..base+3 all < NN (12500*4 == 50000)

#pragma unroll
        for (int q = 0; q < 4; q++) {
            int node = base + q;
            float4 acc = make_float4(0.f, 0.f, 0.f, 0.f);
            int e0 = g_rowptr[node], e1 = g_rowptr[node + 1];
            for (int eb = e0; eb < e1; eb += 32) {
                int ee = eb + lane;
                bool okl = ee < e1;
                int cc = okl ? g_col[ee] : 0;
                float vv = okl ? g_val[ee] : 0.f;
                int cn = min(32, e1 - eb);
                for (int j = 0; j < cn; j += 8) {
                    int sA = __shfl_sync(0xffffffffu, cc, j + hl);
                    int sB = __shfl_sync(0xffffffffu, cc, j + 2 + hl);
                    int sC = __shfl_sync(0xffffffffu, cc, j + 4 + hl);
                    int sD = __shfl_sync(0xffffffffu, cc, j + 6 + hl);
                    float vA = __shfl_sync(0xffffffffu, vv, j + hl);
                    float vB = __shfl_sync(0xffffffffu, vv, j + 2 + hl);
                    float vC = __shfl_sync(0xffffffffu, vv, j + 4 + hl);
                    float vD = __shfl_sync(0xffffffffu, vv, j + 6 + hl);
                    float4 hA = hin4[sA * 16 + fl];
                    float4 hB = hin4[sB * 16 + fl];
                    float4 hC = hin4[sC * 16 + fl];
                    float4 hD = hin4[sD * 16 + fl];
                    acc.x += vA * hA.x; acc.y += vA * hA.y;
                    acc.z += vA * hA.z; acc.w += vA * hA.w;
                    acc.x += vB * hB.x; acc.y += vB * hB.y;
                    acc.z += vB * hB.z; acc.w += vB * hB.w;
                    acc.x += vC * hC.x; acc.y += vC * hC.y;
                    acc.z += vC * hC.z; acc.w += vC * hC.w;
                    acc.x += vD * hD.x; acc.y += vD * hD.y;
                    acc.z += vD * hD.z; acc.w += vD * hD.w;
                }
            }
            acc.x += __shfl_xor_sync(0xffffffffu, acc.x, 16);
            acc.y += __shfl_xor_sync(0xffffffffu, acc.y, 16);
            acc.z += __shfl_xor_sync(0xffffffffu, acc.z, 16);
            acc.w += __shfl_xor_sync(0xffffffffu, acc.w, 16);
            if (hl == 0) {
                float di = g_dinv[node];
                float dd = di * di;
                float4 hme = hin4[node * 16 + fl];
                float4 xm = x04[node * 16 + fl];
                zqf[w][(fl * 4 + 0) * 4 + q] = 0.5f * (acc.x + dd * hme.x) + 0.5f * xm.x;
                zqf[w][(fl * 4 + 1) * 4 + q] = 0.5f * (acc.y + dd * hme.y) + 0.5f * xm.y;
                zqf[w][(fl * 4 + 2) * 4 + q] = 0.5f * (acc.z + dd * hme.z) + 0.5f * xm.z;
                zqf[w][(fl * 4 + 3) * 4 + q] = 0.5f * (acc.w + dd * hme.w) + 0.5f * xm.w;
            }
        }
        __syncwarp();

        float4 s0 = make_float4(0.f, 0.f, 0.f, 0.f);  // out col l2, nodes A..D
        float4 s1 = make_float4(0.f, 0.f, 0.f, 0.f);  // out col l2+1
#pragma unroll
        for (int k = 0; k < 64; k++) {
            float4 zk = *(const float4*)&zqf[w][k * 4];
            float2 wk = *(const float2*)&ws[k * 64 + l2];
            s0.x += zk.x * wk.x; s0.y += zk.y * wk.x;
            s0.z += zk.z * wk.x; s0.w += zk.w * wk.x;
            s1.x += zk.x * wk.y; s1.y += zk.y * wk.y;
            s1.z += zk.z * wk.y; s1.w += zk.w * wk.y;
        }
        float4 zc0 = *(const float4*)&zqf[w][l2 * 4];
        float4 zc1 = *(const float4*)&zqf[w][(l2 + 1) * 4];
        float zr0[4] = {zc0.x, zc0.y, zc0.z, zc0.w};
        float zr1[4] = {zc1.x, zc1.y, zc1.z, zc1.w};
        float sc0[4] = {s0.x, s0.y, s0.z, s0.w};
        float sc1[4] = {s1.x, s1.y, s1.z, s1.w};
#pragma unroll
        for (int q = 0; q < 4; q++) {
            int node = base + q;
            float o0 = fmaxf(ob * zr0[q] + beta * sc0[q], 0.f);
            float o1 = fmaxf(ob * zr1[q] + beta * sc1[q], 0.f);
            *(float2*)&hout[node * 64 + l2] = make_float2(o0, o1);
        }
        __syncwarp();
    }
}

// ---------------- output: lin2 + log_softmax ----------------
__global__ __launch_bounds__(256) void k_out(const float* __restrict__ w2,
                                             const float* __restrict__ b2,
                                             float* __restrict__ out) {
    __shared__ float ws[64 * OC];
    __shared__ float bs[OC];
    __shared__ float zsm[8][64];
    int t = threadIdx.x, w = t >> 5, lane = t & 31;
    for (int i = t; i < 64 * OC; i += 256) ws[i] = w2[i];
    if (t < OC) bs[t] = b2[t];
    __syncthreads();

    const float* h = g_hbuf[0];  // NL even -> final state in buffer 0
    int warpG = blockIdx.x * 8 + w;
    int nW = gridDim.x * 8;

    for (int node = warpG; node < NN; node += nW) {
        float2 h2 = *(const float2*)&h[node * 64 + lane * 2];
        *(float2*)&zsm[w][lane * 2] = h2;
        __syncwarp();
        int c0 = lane;
        int c1 = lane + 32;
        float v0 = bs[c0];
        float v1 = (lane < 8) ? bs[c1] : 0.f;
#pragma unroll
        for (int k = 0; k < 64; k++) {
            float zk = zsm[w][k];
            v0 += zk * ws[k * OC + c0];
            if (lane < 8) v1 += zk * ws[k * OC + c1];
        }
        float m = v0;
        if (lane < 8) m = fmaxf(m, v1);
#pragma unroll
        for (int o = 16; o > 0; o >>= 1)
            m = fmaxf(m, __shfl_xor_sync(0xffffffffu, m, o));
        float se = expf(v0 - m) + ((lane < 8) ? expf(v1 - m) : 0.f);
#pragma unroll
        for (int o = 16; o > 0; o >>= 1)
            se += __shfl_xor_sync(0xffffffffu, se, o);
        float lse = m + logf(se);
        out[node * OC + c0] = v0 - lse;
        if (lane < 8) out[node * OC + c1] = v1 - lse;
        __syncwarp();
    }
}

// ---------------- launch ----------------
extern "C" void kernel_launch(void* const* d_in, const int* in_sizes, int n_in,
                              void* d_out, int out_size) {
    (void)in_sizes; (void)n_in; (void)out_size;
    const float* x  = (const float*)d_in[0];
    const void*  ei = d_in[1];
    const float* w1 = (const float*)d_in[2];
    const float* b1 = (const float*)d_in[3];
    const float* cw = (const float*)d_in[4];
    const float* w2 = (const float*)d_in[5];
    const float* b2 = (const float*)d_in[6];
    float* out = (float*)d_out;

    k_lin1<<<(NN + 127) / 128, 256>>>(x, w1, b1, (const int*)ei);  // #0
    k_count<<<(EE + 255) / 256, 256>>>(ei);                         // #1
    k_scan<<<NBLK, 1024>>>();                                       // #2
    k_fill<<<(EE + 255) / 256, 256>>>(ei);                          // #3

    for (int l = 0; l < NL; l++) {                                  // #4 (l=0), #5 (l=1: profiled)
        float beta = logf(1.0f / (float)(l + 1) + 1.0f);
        k_layer<<<148 * 8, 256>>>(cw + (size_t)l * HH * HH, beta, l, l & 1);
    }
    k_out<<<512, 256>>>(w2, b2, out);
}

// round 7
// speedup vs baseline: 1.0922x; 1.0922x over previous
#include <cuda_runtime.h>
#include <cuda_bf16.h>
#include <math.h>

#define NN  50000
#define EE  800000
#define INC 512
#define HH  64
#define OC  40
#define NL  64
#define NBLK ((NN + 1023) / 1024)       // 49 scan blocks
#define EEP (EE + 7 * NN + 16)          // padded CSR capacity + prefetch slack

// ---------------- device scratch ----------------
__device__ float g_dinv[NN];
__device__ int   g_cnt[NN];
__device__ int   g_rowptr[NN + 1];
__device__ int   g_bsum[NBLK];
__device__ int   g_flag[64];
__device__ int   g_fill[NN];
__device__ int2  g_edge[EEP];           // (col, val-bits), node lists padded to 8
__device__ float g_x0[NN * HH];
__device__ float g_hbuf[2][NN * HH];
__device__ int   g_is64;

// ---------------- launch 0: lin1 (+ zero counts + int64 detect) ----------------
__global__ __launch_bounds__(256) void k_lin1(const float* __restrict__ x,
                                              const float* __restrict__ w1,
                                              const float* __restrict__ b1,
                                              const int* __restrict__ ei32) {
    int gtid = blockIdx.x * 256 + threadIdx.x;
    if (gtid < NN) g_cnt[gtid] = 0;
    if (gtid == 0) {
        int all0 = 1;
        for (int j = 0; j < 64; j++)
            if (ei32[2 * j + 1] != 0) all0 = 0;
        g_is64 = all0;
    }

    __shared__ float xsT[32][129];
    __shared__ float ws[32 * 64];
    int t = threadIdx.x;
    int half = t >> 7;
    int nl = t & 127;
    int node0 = blockIdx.x * 128;

    float acc[32];
#pragma unroll
    for (int c = 0; c < 32; c++) acc[c] = 0.f;

    for (int kt = 0; kt < INC; kt += 32) {
        for (int i = t; i < 32 * 64; i += 256)
            ws[i] = w1[(kt + (i >> 6)) * 64 + (i & 63)];
        for (int i = t; i < 1024; i += 256) {
            int r = i >> 3, c4 = i & 7;
            int node = node0 + r;
            float4 v = make_float4(0.f, 0.f, 0.f, 0.f);
            if (node < NN)
                v = *(const float4*)&x[(size_t)node * INC + kt + c4 * 4];
            xsT[c4 * 4 + 0][r] = v.x;
            xsT[c4 * 4 + 1][r] = v.y;
            xsT[c4 * 4 + 2][r] = v.z;
            xsT[c4 * 4 + 3][r] = v.w;
        }
        __syncthreads();
#pragma unroll 4
        for (int k = 0; k < 32; k++) {
            float xv = xsT[k][nl];
            const float4* wr = (const float4*)&ws[k * 64 + half * 32];
#pragma unroll
            for (int c4 = 0; c4 < 8; c4++) {
                float4 w4 = wr[c4];
                acc[c4 * 4 + 0] += xv * w4.x;
                acc[c4 * 4 + 1] += xv * w4.y;
                acc[c4 * 4 + 2] += xv * w4.z;
                acc[c4 * 4 + 3] += xv * w4.w;
            }
        }
        __syncthreads();
    }
    int node = node0 + nl;
    if (node < NN) {
        float* px = &g_x0[node * 64 + half * 32];
        float* ph = &g_hbuf[0][node * 64 + half * 32];
#pragma unroll
        for (int c4 = 0; c4 < 8; c4++) {
            float4 v;
            v.x = fmaxf(acc[c4 * 4 + 0] + b1[half * 32 + c4 * 4 + 0], 0.f);
            v.y = fmaxf(acc[c4 * 4 + 1] + b1[half * 32 + c4 * 4 + 1], 0.f);
            v.z = fmaxf(acc[c4 * 4 + 2] + b1[half * 32 + c4 * 4 + 2], 0.f);
            v.w = fmaxf(acc[c4 * 4 + 3] + b1[half * 32 + c4 * 4 + 3], 0.f);
            *(float4*)&px[c4 * 4] = v;
            *(float4*)&ph[c4 * 4] = v;
        }
    }
}

// ---------------- launch 1: count (+ reset lookback flags + slack zero) ----------------
__global__ void k_count(const void* eiv) {
    int e = blockIdx.x * blockDim.x + threadIdx.x;
    if (e < 64) g_flag[e] = 0;
    if (e < 16) g_edge[EEP - 16 + e] = make_int2(0, 0);  // prefetch slack
    if (e >= EE) return;
    int d;
    if (g_is64) d = (int)((const long long*)eiv)[EE + e];
    else        d = ((const int*)eiv)[EE + e];
    atomicAdd(&g_cnt[d], 1);
}

// ---------------- launch 2: single-pass scan over PADDED counts ----------------
// also: dinv, fill=0, zero the pad slots, rowptr[NN]
__global__ __launch_bounds__(1024) void k_scan() {
    __shared__ int wsum[32];
    __shared__ int pred[64];
    int t = threadIdx.x, b = blockIdx.x;
    int i = b * 1024 + t;
    int c = (i < NN) ? g_cnt[i] : 0;
    int v = (c + 7) & ~7;               // padded degree
    int lane = t & 31, wid = t >> 5;
    int s = v;
#pragma unroll
    for (int o = 1; o < 32; o <<= 1) {
        int u = __shfl_up_sync(0xffffffffu, s, o);
        if (lane >= o) s += u;
    }
    if (lane == 31) wsum[wid] = s;
    __syncthreads();
    if (wid == 0) {
        int ws = wsum[lane];
#pragma unroll
        for (int o = 1; o < 32; o <<= 1) {
            int u = __shfl_up_sync(0xffffffffu, ws, o);
            if (lane >= o) ws += u;
        }
        wsum[lane] = ws;
    }
    __syncthreads();
    int excl = s - v + (wid > 0 ? wsum[wid - 1] : 0);
    if (t == 1023) {
        g_bsum[b] = excl + v;
        __threadfence();
        atomicExch(&g_flag[b], 1);
    }
    if (t < 64) {
        int pv = 0;
        if (t < b) {
            while (atomicAdd(&g_flag[t], 0) == 0) {}
            pv = g_bsum[t];
        }
        pred[t] = pv;
    }
    __syncthreads();
    for (int o = 32; o > 0; o >>= 1) {
        if (t < o) pred[t] += pred[t + o];
        __syncthreads();
    }
    int off = pred[0];
    if (i < NN) {
        int rp = excl + off;
        g_rowptr[i] = rp;
        g_dinv[i] = rsqrtf((float)(c + 1));
        g_fill[i] = 0;
        for (int j = c; j < v; j++)          // zero the pad slots
            g_edge[rp + j] = make_int2(0, 0);
        if (i == NN - 1) g_rowptr[NN] = rp + v;
    }
}

// ---------------- launch 3: fill CSR ----------------
__global__ void k_fill(const void* eiv) {
    int e = blockIdx.x * blockDim.x + threadIdx.x;
    if (e >= EE) return;
    int s, d;
    if (g_is64) {
        const long long* ei = (const long long*)eiv;
        s = (int)ei[e];
        d = (int)ei[EE + e];
    } else {
        const int* ei = (const int*)eiv;
        s = ei[e];
        d = ei[EE + e];
    }
    int pos = g_rowptr[d] + atomicAdd(&g_fill[d], 1);
    g_edge[pos] = make_int2(s, __float_as_int(g_dinv[s] * g_dinv[d]));
}

// ---------------- launches 4..: fused GCNII layer ----------------
// warp = 4 nodes (static). Uniform-broadcast edge loads from padded CSR,
// software-pipelined; lane owns feature quad fl, half-warps split edges.
__global__ __launch_bounds__(256) void k_layer(const float* __restrict__ W,
                                               float beta, int p) {
    __shared__ float ws[64 * 64];
    __shared__ float4 zq[8][64];
    int t = threadIdx.x, w = t >> 5, lane = t & 31;
    int l2 = lane * 2;
    int hl = lane >> 4;          // edge parity within pair
    int fl = lane & 15;          // feature quad id
    for (int i = t; i < 4096; i += 256) ws[i] = W[i];
    __syncthreads();

    const float4* __restrict__ hin4 = (const float4*)g_hbuf[p];
    const float4* __restrict__ x04 = (const float4*)g_x0;
    float* __restrict__ hout = g_hbuf[p ^ 1];
    int warpG = blockIdx.x * 8 + w;
    int nW = gridDim.x * 8;
    float ob = 1.f - beta;

    for (int base = warpG * 4; base < NN; base += nW * 4) {
        // fetch the 5 rowptrs for this bundle once
        int rp = 0;
        if (lane < 5) rp = g_rowptr[base + lane];
        float4 z4[4];
#pragma unroll
        for (int q = 0; q < 4; q++) {
            int node = base + q;              // NN % 4 == 0 -> always valid
            int e0 = __shfl_sync(0xffffffffu, rp, q);
            int e1 = __shfl_sync(0xffffffffu, rp, q + 1);
            int pd = e1 - e0;                 // multiple of 8
            float4 acc = make_float4(0.f, 0.f, 0.f, 0.f);
            if (pd > 0) {
                const int2* ep = g_edge + e0;
                int2 eA = ep[hl], eB = ep[2 + hl], eC = ep[4 + hl], eD = ep[6 + hl];
                for (int j = 8;; j += 8) {
                    // prefetch next group (slack slots make overread safe)
                    int2 nA = ep[j + hl];
                    int2 nB = ep[j + 2 + hl];
                    int2 nC = ep[j + 4 + hl];
                    int2 nD = ep[j + 6 + hl];
                    float4 hA = hin4[eA.x * 16 + fl];
                    float4 hB = hin4[eB.x * 16 + fl];
                    float4 hC = hin4[eC.x * 16 + fl];
                    float4 hD = hin4[eD.x * 16 + fl];
                    float vA = __int_as_float(eA.y);
                    float vB = __int_as_float(eB.y);
                    float vC = __int_as_float(eC.y);
                    float vD = __int_as_float(eD.y);
                    acc.x += vA * hA.x; acc.y += vA * hA.y;
                    acc.z += vA * hA.z; acc.w += vA * hA.w;
                    acc.x += vB * hB.x; acc.y += vB * hB.y;
                    acc.z += vB * hB.z; acc.w += vB * hB.w;
                    acc.x += vC * hC.x; acc.y += vC * hC.y;
                    acc.z += vC * hC.z; acc.w += vC * hC.w;
                    acc.x += vD * hD.x; acc.y += vD * hD.y;
                    acc.z += vD * hD.z; acc.w += vD * hD.w;
                    if (j >= pd) break;
                    eA = nA; eB = nB; eC = nC; eD = nD;
                }
            }
            // combine the two half-warp partials
            acc.x += __shfl_xor_sync(0xffffffffu, acc.x, 16);
            acc.y += __shfl_xor_sync(0xffffffffu, acc.y, 16);
            acc.z += __shfl_xor_sync(0xffffffffu, acc.z, 16);
            acc.w += __shfl_xor_sync(0xffffffffu, acc.w, 16);
            if (hl == 0) {
                float di = g_dinv[node];
                float dd = di * di;
                float4 hme = hin4[node * 16 + fl];
                float4 xm = x04[node * 16 + fl];
                z4[q].x = 0.5f * (acc.x + dd * hme.x) + 0.5f * xm.x;
                z4[q].y = 0.5f * (acc.y + dd * hme.y) + 0.5f * xm.y;
                z4[q].z = 0.5f * (acc.z + dd * hme.z) + 0.5f * xm.z;
                z4[q].w = 0.5f * (acc.w + dd * hme.w) + 0.5f * xm.w;
            }
        }
        // stage transposed: zq[k] = {zA[k], zB[k], zC[k], zD[k]}
        if (hl == 0) {
            zq[w][fl * 4 + 0] = make_float4(z4[0].x, z4[1].x, z4[2].x, z4[3].x);
            zq[w][fl * 4 + 1] = make_float4(z4[0].y, z4[1].y, z4[2].y, z4[3].y);
            zq[w][fl * 4 + 2] = make_float4(z4[0].z, z4[1].z, z4[2].z, z4[3].z);
            zq[w][fl * 4 + 3] = make_float4(z4[0].w, z4[1].w, z4[2].w, z4[3].w);
        }
        __syncwarp();

        float4 s0 = make_float4(0.f, 0.f, 0.f, 0.f);  // out col l2, nodes A..D
        float4 s1 = make_float4(0.f, 0.f, 0.f, 0.f);  // out col l2+1
#pragma unroll
        for (int k = 0; k < 64; k++) {
            float4 zk = zq[w][k];
            float2 wk = *(const float2*)&ws[k * 64 + l2];
            s0.x += zk.x * wk.x; s0.y += zk.y * wk.x;
            s0.z += zk.z * wk.x; s0.w += zk.w * wk.x;
            s1.x += zk.x * wk.y; s1.y += zk.y * wk.y;
            s1.z += zk.z * wk.y; s1.w += zk.w * wk.y;
        }
        float4 zc0 = zq[w][l2];
        float4 zc1 = zq[w][l2 + 1];
        float zr0[4] = {zc0.x, zc0.y, zc0.z, zc0.w};
        float zr1[4] = {zc1.x, zc1.y, zc1.z, zc1.w};
        float sc0[4] = {s0.x, s0.y, s0.z, s0.w};
        float sc1[4] = {s1.x, s1.y, s1.z, s1.w};
#pragma unroll
        for (int q = 0; q < 4; q++) {
            int node = base + q;
            float o0 = fmaxf(ob * zr0[q] + beta * sc0[q], 0.f);
            float o1 = fmaxf(ob * zr1[q] + beta * sc1[q], 0.f);
            *(float2*)&hout[node * 64 + l2] = make_float2(o0, o1);
        }
        __syncwarp();
    }
}

// ---------------- output: lin2 + log_softmax ----------------
__global__ __launch_bounds__(256) void k_out(const float* __restrict__ w2,
                                             const float* __restrict__ b2,
                                             float* __restrict__ out) {
    __shared__ float ws[64 * OC];
    __shared__ float bs[OC];
    __shared__ float zsm[8][64];
    int t = threadIdx.x, w = t >> 5, lane = t & 31;
    for (int i = t; i < 64 * OC; i += 256) ws[i] = w2[i];
    if (t < OC) bs[t] = b2[t];
    __syncthreads();

    const float* h = g_hbuf[0];  // NL even -> final state in buffer 0
    int warpG = blockIdx.x * 8 + w;
    int nW = gridDim.x * 8;

    for (int node = warpG; node < NN; node += nW) {
        float2 h2 = *(const float2*)&h[node * 64 + lane * 2];
        *(float2*)&zsm[w][lane * 2] = h2;
        __syncwarp();
        int c0 = lane;
        int c1 = lane + 32;
        float v0 = bs[c0];
        float v1 = (lane < 8) ? bs[c1] : 0.f;
#pragma unroll
        for (int k = 0; k < 64; k++) {
            float zk = zsm[w][k];
            v0 += zk * ws[k * OC + c0];
            if (lane < 8) v1 += zk * ws[k * OC + c1];
        }
        float m = v0;
        if (lane < 8) m = fmaxf(m, v1);
#pragma unroll
        for (int o = 16; o > 0; o >>= 1)
            m = fmaxf(m, __shfl_xor_sync(0xffffffffu, m, o));
        float se = expf(v0 - m) + ((lane < 8) ? expf(v1 - m) : 0.f);
#pragma unroll
        for (int o = 16; o > 0; o >>= 1)
            se += __shfl_xor_sync(0xffffffffu, se, o);
        float lse = m + logf(se);
        out[node * OC + c0] = v0 - lse;
        if (lane < 8) out[node * OC + c1] = v1 - lse;
        __syncwarp();
    }
}

// ---------------- launch ----------------
extern "C" void kernel_launch(void* const* d_in, const int* in_sizes, int n_in,
                              void* d_out, int out_size) {
    (void)in_sizes; (void)n_in; (void)out_size;
    const float* x  = (const float*)d_in[0];
    const void*  ei = d_in[1];
    const float* w1 = (const float*)d_in[2];
    const float* b1 = (const float*)d_in[3];
    const float* cw = (const float*)d_in[4];
    const float* w2 = (const float*)d_in[5];
    const float* b2 = (const float*)d_in[6];
    float* out = (float*)d_out;

    k_lin1<<<(NN + 127) / 128, 256>>>(x, w1, b1, (const int*)ei);  // #0
    k_count<<<(EE + 255) / 256, 256>>>(ei);                         // #1
    k_scan<<<NBLK, 1024>>>();                                       // #2
    k_fill<<<(EE + 255) / 256, 256>>>(ei);                          // #3

    for (int l = 0; l < NL; l++) {                                  // #4.. (#5 = layer 1)
        float beta = logf(1.0f / (float)(l + 1) + 1.0f);
        k_layer<<<148 * 8, 256>>>(cw + (size_t)l * HH * HH, beta, l & 1);
    }
    k_out<<<512, 256>>>(w2, b2, out);
}